// round 12
// baseline (speedup 1.0000x reference)
#include <cuda_runtime.h>

// Problem constants
#define HH   112
#define WW   112
#define CROP 28
#define CW   56
#define NPIX (CW * CW)
#define BB   128
#define MM   64
#define TT   12
#define HID  64
#define OUTD 36

#define NTHR 128
#define AUX_BLOCKS BB            // 1 block per batch
#define MOT_BLOCKS 4
#define NBLK (AUX_BLOCKS + MOT_BLOCKS)   // 132 <= 148 : one wave

#define TABN 400                 // distance-table entries

__device__ float g_aux_partial[AUX_BLOCKS];
__device__ float g_mot_partial[MOT_BLOCKS];
__device__ int   g_count = 0;

#define FMA2(acc, x, y) \
    asm("fma.rn.f32x2 %0, %1, %2, %0;" : "+l"(acc) : "l"(x), "l"(y))

__global__ __launch_bounds__(NTHR) void fused_kernel(
    const int*   __restrict__ goal_pixel,   // [B,2] (col,row)
    const int*   __restrict__ obj_list,     // [B,M,2] (col,row)
    const int*   __restrict__ obj_num,      // [B]
    const int*   __restrict__ road_mask,    // [B,112,112]
    const float* __restrict__ logits,       // [B,56,56]
    const float* __restrict__ tpos,         // [B,T,2]
    const float* __restrict__ tyaw,         // [B,T]
    const float* __restrict__ w1, const float* __restrict__ b1,
    const float* __restrict__ w2, const float* __restrict__ b2,
    float*       __restrict__ out)
{
    const int blk = blockIdx.x;
    const int tid = threadIdx.x;

    // Batch-INDEPENDENT distance tables (e(j) = exp(-(j-140)^2/8); the
    // center is 140 so j = pixel + (140 - objcoord) stays in [29, 400)).
    __shared__ __align__(16) float4 tabq[TABN];   // (e,e+1,e+2,e+3)  6.4KB
    __shared__ __align__(16) float4 tabd2[TABN];  // (e,e,e+1,e+1)    6.4KB
    __shared__ float tabc[TABN + 8];              // scalar            1.6KB
    __shared__ int   s_cb[MM], s_rb[MM];          // per-object byte offsets
    __shared__ float s_warp[4];
    __shared__ bool  s_last;

    if (blk < AUX_BLOCKS) {
        // ======== aux: one full 56x56 crop per block ========
        const int b  = blk;
        const int rt = tid >> 4;            // row tile 0..7 (7 valid, 8 rows)
        const int ct = tid & 15;            // col tile 0..15 (14 valid, 4 cols)
        const int rteff = (rt < 7) ? rt : 6;
        const int cteff = (ct < 14) ? ct : 13;

        // ---- phase 0: front-issue ALL global loads ----
        const int yg = goal_pixel[2 * b + 0];
        const int xg = goal_pixel[2 * b + 1];

        int2 ocoord = make_int2(-160, -160);
        int  nobj   = 0;
        if (tid < MM) {
            nobj   = obj_num[b];
            ocoord = ((const int2*)obj_list)[b * MM + tid];
        }

        const int r0e = rteff * 8, c0e = cteff * 4;
        float4 zreg[8];
        int4   mreg[8];
        {
            const float4* lg = (const float4*)(logits + b * NPIX + r0e * CW + c0e);
            const int4*   rm = (const int4*)(road_mask
                               + (b * HH + r0e + CROP) * WW + c0e + CROP);
            #pragma unroll
            for (int k = 0; k < 8; k++) {
                zreg[k] = __ldg(lg + k * (CW / 4));
                mreg[k] = __ldg(rm + k * (WW / 4));
            }
        }

        // ---- phase 1: batch-independent scalar table (overlaps the LDGs) --
        #pragma unroll
        for (int it = 0; it < 4; it++) {
            const int i = it * NTHR + tid;
            if (i < TABN + 8) {
                const float d = (float)(i - 140);
                tabc[i] = __expf(-d * d * 0.125f);
            }
        }
        // coordinate convert (depends on obj LDG already in flight)
        if (tid < MM) {
            nobj = nobj < 0 ? 0 : (nobj > MM ? MM : nobj);
            if (tid >= nobj) { ocoord.x = -160; ocoord.y = -160; }
            s_cb[tid] = (140 + CROP - ocoord.x) * 16;   // col byte offset
            s_rb[tid] = (140 + CROP - ocoord.y) * 16;   // row byte offset
        }
        __syncthreads();

        // ---- phase 2: derived packed tables ----
        #pragma unroll
        for (int it = 0; it < 4; it++) {
            const int i = it * NTHR + tid;
            if (i < TABN) {
                const float a0 = tabc[i],     a1 = tabc[i + 1];
                const float a2 = tabc[i + 2], a3 = tabc[i + 3];
                tabq[i]  = make_float4(a0, a1, a2, a3);
                tabd2[i] = make_float4(a0, a0, a1, a1);
            }
        }
        __syncthreads();

        // ---- phase 3: object loop (16 f32x2 accumulators, 8x4 px) ----
        unsigned long long a[16];
        #pragma unroll
        for (int i = 0; i < 16; i++) a[i] = 0ull;

        // per-thread bases: crop col c0 = ct*4 (x16B), crop row r0 = rteff*8 (x16B)
        const char* bc = (const char*)tabq  + ct * 64;      // + s_cb[m]
        const char* br = (const char*)tabd2 + rteff * 128;  // + s_rb[m]

        #pragma unroll
        for (int mq = 0; mq < 16; mq++) {
            const int4 cb4 = ((const int4*)s_cb)[mq];
            const int4 rb4 = ((const int4*)s_rb)[mq];
            #pragma unroll
            for (int u = 0; u < 4; u++) {
                const int cb = (u == 0) ? cb4.x : (u == 1) ? cb4.y
                             : (u == 2) ? cb4.z : cb4.w;
                const int rb = (u == 0) ? rb4.x : (u == 1) ? rb4.y
                             : (u == 2) ? rb4.z : rb4.w;
                const ulonglong2 cf  = *(const ulonglong2*)(bc + cb);
                const ulonglong2 r01 = *(const ulonglong2*)(br + rb);
                const ulonglong2 r23 = *(const ulonglong2*)(br + rb + 32);
                const ulonglong2 r45 = *(const ulonglong2*)(br + rb + 64);
                const ulonglong2 r67 = *(const ulonglong2*)(br + rb + 96);
                FMA2(a[0],  cf.x, r01.x); FMA2(a[1],  cf.y, r01.x);
                FMA2(a[2],  cf.x, r01.y); FMA2(a[3],  cf.y, r01.y);
                FMA2(a[4],  cf.x, r23.x); FMA2(a[5],  cf.y, r23.x);
                FMA2(a[6],  cf.x, r23.y); FMA2(a[7],  cf.y, r23.y);
                FMA2(a[8],  cf.x, r45.x); FMA2(a[9],  cf.y, r45.x);
                FMA2(a[10], cf.x, r45.y); FMA2(a[11], cf.y, r45.y);
                FMA2(a[12], cf.x, r67.x); FMA2(a[13], cf.y, r67.x);
                FMA2(a[14], cf.x, r67.y); FMA2(a[15], cf.y, r67.y);
            }
        }

        // ---- phase 4: epilogue from registers ----
        float local = 0.0f;
        if (rt < 7 && ct < 14) {
            const int r0 = rt * 8, c0 = ct * 4;
            float gc[4];
            #pragma unroll
            for (int u = 0; u < 4; u++)
                gc[u] = tabc[c0 + u + CROP + 140 - yg];

            #pragma unroll
            for (int k = 0; k < 8; k++) {
                const float4 z4 = zreg[k];
                const int4   m4 = mreg[k];
                const float  gr = tabc[r0 + k + CROP + 140 - xg];
                float s[4];
                asm("mov.b64 {%0, %1}, %2;" : "=f"(s[0]), "=f"(s[1]) : "l"(a[2*k]));
                asm("mov.b64 {%0, %1}, %2;" : "=f"(s[2]), "=f"(s[3]) : "l"(a[2*k+1]));
                const float zz[4] = {z4.x, z4.y, z4.z, z4.w};
                const int   mm[4] = {m4.x, m4.y, m4.z, m4.w};
                #pragma unroll
                for (int u = 0; u < 4; u++) {
                    const float z  = zz[u];
                    const float sp = fmaxf(z, 0.0f)
                                   + __logf(1.0f + __expf(-fabsf(z)));
                    float gt = 0.0f;
                    if (mm[u] != 0)
                        gt = 0.5f + 0.5f * (gc[u] * gr) - 0.5f * s[u];
                    local += sp - z * gt;
                }
            }
        }

        #pragma unroll
        for (int off = 16; off > 0; off >>= 1)
            local += __shfl_down_sync(0xffffffffu, local, off);
        if ((tid & 31) == 0) s_warp[tid >> 5] = local;
        __syncthreads();
        if (tid == 0)
            g_aux_partial[blk] = s_warp[0] + s_warp[1] + s_warp[2] + s_warp[3];
    } else {
        // ======== motion MLP loss (512 lanes over 4 blocks) ========
        const int mt = (blk - AUX_BLOCKS) * NTHR + tid;   // 0..511
        float part = 0.0f;
        {
            const int b  = mt >> 2;
            const int og = mt & 3;

            const float x0 = (float)goal_pixel[2 * b + 0];
            const float x1 = (float)goal_pixel[2 * b + 1];

            float h[HID];
            #pragma unroll
            for (int j = 0; j < HID; j++) {
                float v = fmaf(x0, w1[j], fmaf(x1, w1[HID + j], b1[j]));
                h[j] = fmaxf(v, 0.0f);
            }
            float acc[9];
            #pragma unroll
            for (int u = 0; u < 9; u++) acc[u] = b2[og * 9 + u];
            for (int j = 0; j < HID; j++) {
                const float hv = h[j];
                const float* wr = w2 + j * OUTD + og * 9;
                #pragma unroll
                for (int u = 0; u < 9; u++)
                    acc[u] = fmaf(hv, wr[u], acc[u]);
            }
            #pragma unroll
            for (int u = 0; u < 9; u++) {
                const int o = og * 9 + u;
                const int t = o / 3, uu = o % 3;
                const float tgt = (uu < 2) ? tpos[(b * TT + t) * 2 + uu]
                                           : tyaw[b * TT + t];
                const float d = acc[u] - tgt;
                part = fmaf(d, d, part);
            }
        }
        #pragma unroll
        for (int off = 16; off > 0; off >>= 1)
            part += __shfl_down_sync(0xffffffffu, part, off);
        if ((tid & 31) == 0) s_warp[tid >> 5] = part;
        __syncthreads();
        if (tid == 0)
            g_mot_partial[blk - AUX_BLOCKS] =
                s_warp[0] + s_warp[1] + s_warp[2] + s_warp[3];
    }

    // ======== last-block-done final combine ========
    __syncthreads();
    __threadfence();
    if (tid == 0) {
        int old = atomicAdd(&g_count, 1);
        s_last = (old == NBLK - 1);
    }
    __syncthreads();

    if (s_last) {
        __threadfence();
        float v = g_aux_partial[tid];        // 128 partials, 1 per thread
        #pragma unroll
        for (int off = 16; off > 0; off >>= 1)
            v += __shfl_down_sync(0xffffffffu, v, off);
        if ((tid & 31) == 0) s_warp[tid >> 5] = v;
        __syncthreads();
        if (tid == 0) {
            const float aux = s_warp[0] + s_warp[1] + s_warp[2] + s_warp[3];
            const float mot = (g_mot_partial[0] + g_mot_partial[1]
                             + g_mot_partial[2] + g_mot_partial[3])
                              * (1.0f / (float)(BB * OUTD));
            out[0] = mot + aux;
            out[1] = aux;
            out[2] = mot;
            g_count = 0;   // reset for next graph replay
        }
    }
}

extern "C" void kernel_launch(void* const* d_in, const int* in_sizes, int n_in,
                              void* d_out, int out_size)
{
    const int*   goal_pixel = (const int*)  d_in[0];
    const int*   obj_list   = (const int*)  d_in[1];
    const int*   obj_num    = (const int*)  d_in[2];
    const int*   road_mask  = (const int*)  d_in[3];
    const float* logits     = (const float*)d_in[4];
    const float* tpos       = (const float*)d_in[5];
    const float* tyaw       = (const float*)d_in[6];
    const float* w1         = (const float*)d_in[7];
    const float* b1         = (const float*)d_in[8];
    const float* w2         = (const float*)d_in[9];
    const float* b2         = (const float*)d_in[10];
    float* out = (float*)d_out;

    fused_kernel<<<NBLK, NTHR>>>(goal_pixel, obj_list, obj_num, road_mask,
                                 logits, tpos, tyaw, w1, b1, w2, b2, out);
}